// round 6
// baseline (speedup 1.0000x reference)
#include <cuda_runtime.h>
#include <cuda_fp16.h>
#include <mma.h>
#include <cstdint>

using namespace nvcuda;

#define NN 8192
#define CC 256

// ---------------------------------------------------------------------------
// Scratch (__device__ globals; allocation-free rule)
// ---------------------------------------------------------------------------
__device__ float  g_s[NN];                 // d^{-1/2}
__device__ __half g_xsh[NN * CC];          // fp16(s_j * x[j][n])  [K][N]
__device__ __half g_a2h[NN * CC];          // fp16(s_i*(t + s_i*x)) [M][K]
__device__ __half g_wh[CC * CC];           // fp16(w)  [K][N]

// ---------------------------------------------------------------------------
__device__ __forceinline__ uint32_t smem_u32(const void* p) {
    uint32_t a;
    asm("{ .reg .u64 t; cvta.to.shared.u64 t, %1; cvt.u32.u64 %0, t; }" : "=r"(a) : "l"(p));
    return a;
}
__device__ __forceinline__ void cpa16(uint32_t s, const void* g) {
    asm volatile("cp.async.cg.shared.global [%0], [%1], 16;" :: "r"(s), "l"(g));
}
#define CP_COMMIT() asm volatile("cp.async.commit_group;" ::: "memory")
#define CP_WAIT_2() asm volatile("cp.async.wait_group 2;" ::: "memory")

// ---------------------------------------------------------------------------
// Kernel 1: s[i] = rsqrt(1 + rowsum(adj[i,:]))   (pure read, no convert)
// ---------------------------------------------------------------------------
__global__ void rowsum_kernel(const float* __restrict__ adj) {
    const int row = blockIdx.x * blockDim.y + threadIdx.y;
    const float4* p = reinterpret_cast<const float4*>(adj + (size_t)row * NN);
    float sum = 0.0f;
#pragma unroll 4
    for (int i = threadIdx.x; i < NN / 4; i += 32) {
        float4 v = p[i];
        sum += (v.x + v.y) + (v.z + v.w);
    }
#pragma unroll
    for (int o = 16; o > 0; o >>= 1) sum += __shfl_xor_sync(0xffffffffu, sum, o);
    if (threadIdx.x == 0) g_s[row] = rsqrtf(sum + 1.0f);
}

// ---------------------------------------------------------------------------
__global__ void prep_xs_kernel(const float* __restrict__ x) {
    const int idx = blockIdx.x * 256 + threadIdx.x;   // over NN*CC/4 float4s
    const int row = idx >> 6;                          // CC/4 = 64 per row
    const float s = g_s[row];
    float4 v = reinterpret_cast<const float4*>(x)[idx];
    __half2 h0 = __floats2half2_rn(s * v.x, s * v.y);
    __half2 h1 = __floats2half2_rn(s * v.z, s * v.w);
    uint2 u;
    u.x = *reinterpret_cast<uint32_t*>(&h0);
    u.y = *reinterpret_cast<uint32_t*>(&h1);
    reinterpret_cast<uint2*>(g_xsh)[idx] = u;
}

__global__ void prep_w_kernel(const float* __restrict__ w) {
    const int idx = blockIdx.x * 256 + threadIdx.x;   // over CC*CC/4 float4s
    float4 v = reinterpret_cast<const float4*>(w)[idx];
    __half2 h0 = __floats2half2_rn(v.x, v.y);
    __half2 h1 = __floats2half2_rn(v.z, v.w);
    uint2 u;
    u.x = *reinterpret_cast<uint32_t*>(&h0);
    u.y = *reinterpret_cast<uint32_t*>(&h1);
    reinterpret_cast<uint2*>(g_wh)[idx] = u;
}

// ---------------------------------------------------------------------------
// fp16 WMMA GEMM, tile 128x128, BK=64, 4-stage pipeline.
//   MODE 0: A = adj (f32, register-staged LDG -> cvt fp16 -> STS); epilogue
//           writes g_a2h = fp16( s_i * (D + s_i * x) )
//   MODE 1: A = g_a2h (fp16 via cp.async); epilogue writes out = ELU(D) (f32)
// 256 threads = 8 warps as 4(M) x 2(N); warp tile 32x64.
// ---------------------------------------------------------------------------
constexpr int BM = 128, BN = 128, BK = 64, STAGES = 4;
constexpr int APAD = 72;                   // A smem row stride (halves)
constexpr int BPAD = 136;                  // B smem row stride (halves)
constexpr int A_HALVES = BM * APAD;        // 9216
constexpr int B_HALVES = BK * BPAD;        // 8704
constexpr int STAGE_BYTES = (A_HALVES + B_HALVES) * 2;   // 35840
constexpr int SMEM_BYTES = STAGES * STAGE_BYTES;          // 143360

template <int MODE>
__global__ __launch_bounds__(256, 1)
void gemm_fp16(const float* __restrict__ A32, const __half* __restrict__ A16,
               const __half* __restrict__ B, int k_iters,
               const float* __restrict__ xin, float* __restrict__ outp) {
    extern __shared__ char smem[];
    const uint32_t sb = smem_u32(smem);
    const int tid = threadIdx.x;
    const int warp = tid >> 5;
    const int wm = warp & 3;     // 0..3 along M
    const int wn = warp >> 2;    // 0..1 along N
    const int m0 = blockIdx.y * BM;
    const int n0 = blockIdx.x * BN;

    // ---- A path coordinates ----
    // MODE 0 (f32 LDG): thread -> row ar=tid>>1 (0..127), cols ac=(tid&1)*32 .. +31
    const int ar = tid >> 1, ac = (tid & 1) * 32;
    const float* gA32 = A32 + (size_t)(m0 + ar) * NN + ac;
    // MODE 1 (fp16 cp.async): 128r x 8 chunks of 16B
    const int arr = tid >> 3, arc = (tid & 7) * 8;
    const __half* gA16 = A16 + (size_t)(m0 + arr) * CC + arc;
    const uint32_t sAo = (arr * APAD + arc) * 2;
    // B: 64r x 16 chunks of 16B
    const int brr = tid >> 4, brc = (tid & 15) * 8;
    const __half* gB = B + (size_t)brr * CC + n0 + brc;
    const uint32_t sBo = A_HALVES * 2 + (brr * BPAD + brc) * 2;

    float4 areg[8];   // MODE 0: staged A chunk (32 floats)

    auto ldgA = [&](int kt) {
        const float* a = gA32 + (size_t)kt * BK;
#pragma unroll
        for (int q = 0; q < 8; q++)
            areg[q] = *reinterpret_cast<const float4*>(a + q * 4);
    };
    auto stsA = [&](int s) {
        char* d = smem + s * STAGE_BYTES + (ar * APAD + ac) * 2;
#pragma unroll
        for (int q = 0; q < 8; q++) {
            __half2 h0 = __floats2half2_rn(areg[q].x, areg[q].y);
            __half2 h1 = __floats2half2_rn(areg[q].z, areg[q].w);
            uint2 u;
            u.x = *reinterpret_cast<uint32_t*>(&h0);
            u.y = *reinterpret_cast<uint32_t*>(&h1);
            *reinterpret_cast<uint2*>(d + q * 8) = u;
        }
    };
    auto loadA16 = [&](int kt, int s) {
        const uint32_t st = sb + s * STAGE_BYTES;
        const __half* a = gA16 + kt * BK;
#pragma unroll
        for (int r = 0; r < 4; r++)
            cpa16(st + sAo + r * (32 * APAD * 2), a + (size_t)(r * 32) * CC);
    };
    auto loadB = [&](int kt, int s) {
        const uint32_t st = sb + s * STAGE_BYTES;
        const __half* b = gB + (size_t)kt * BK * CC;
#pragma unroll
        for (int r = 0; r < 4; r++)
            cpa16(st + sBo + r * (16 * BPAD * 2), b + (size_t)(r * 16) * CC);
    };

    wmma::fragment<wmma::accumulator, 16, 16, 16, float> acc[2][4];
#pragma unroll
    for (int i = 0; i < 2; i++)
#pragma unroll
        for (int j = 0; j < 4; j++) wmma::fill_fragment(acc[i][j], 0.0f);

    // ---- prologue ----
    if (MODE == 0) {
        ldgA(0); stsA(0);
        ldgA(1); stsA(1);
        ldgA(2);                       // stage 2 kept in regs, STS'd at kt=0
    }
#pragma unroll
    for (int s = 0; s < STAGES - 1; s++) {
        if (s < k_iters) {
            if (MODE == 1) loadA16(s, s);
            loadB(s, s);
        }
        CP_COMMIT();
    }

    // ---- mainloop ----
    for (int kt = 0; kt < k_iters; kt++) {
        CP_WAIT_2();
        __syncthreads();

        if (MODE == 0) {
            if (kt + 2 < k_iters) stsA(kt + 2 < STAGES ? kt + 2 : (kt + 2) & 3);
            if (kt + 3 < k_iters) ldgA(kt + 3);
            if (kt + 3 < k_iters) loadB(kt + 3, (kt + 3) & 3);
        } else {
            if (kt + 3 < k_iters) { loadA16(kt + 3, (kt + 3) & 3); loadB(kt + 3, (kt + 3) & 3); }
        }
        CP_COMMIT();

        const __half* Ap = reinterpret_cast<const __half*>(smem + (kt & 3) * STAGE_BYTES);
        const __half* Bp = Ap + A_HALVES;

        wmma::fragment<wmma::matrix_a, 16, 16, 16, __half, wmma::row_major> af[2][2];
        wmma::fragment<wmma::matrix_b, 16, 16, 16, __half, wmma::row_major> bf[2][4];
#pragma unroll
        for (int i = 0; i < 2; i++)
            wmma::load_matrix_sync(af[0][i], Ap + (wm * 32 + i * 16) * APAD, APAD);
#pragma unroll
        for (int j = 0; j < 4; j++)
            wmma::load_matrix_sync(bf[0][j], Bp + wn * 64 + j * 16, BPAD);

#pragma unroll
        for (int ks = 0; ks < 4; ks++) {
            const int cu = ks & 1, nx = cu ^ 1;
            if (ks < 3) {
#pragma unroll
                for (int i = 0; i < 2; i++)
                    wmma::load_matrix_sync(af[nx][i],
                        Ap + (wm * 32 + i * 16) * APAD + (ks + 1) * 16, APAD);
#pragma unroll
                for (int j = 0; j < 4; j++)
                    wmma::load_matrix_sync(bf[nx][j],
                        Bp + ((ks + 1) * 16) * BPAD + wn * 64 + j * 16, BPAD);
            }
#pragma unroll
            for (int i = 0; i < 2; i++)
#pragma unroll
                for (int j = 0; j < 4; j++)
                    wmma::mma_sync(acc[i][j], af[cu][i], bf[cu][j], acc[i][j]);
        }
    }
    __syncthreads();

    // ---- epilogue ----
    float* stg = reinterpret_cast<float*>(smem);   // 128 x 132
#pragma unroll
    for (int i = 0; i < 2; i++)
#pragma unroll
        for (int j = 0; j < 4; j++)
            wmma::store_matrix_sync(stg + (wm * 32 + i * 16) * 132 + wn * 64 + j * 16,
                                    acc[i][j], 132, wmma::mem_row_major);
    __syncthreads();

    const int r = tid >> 1;             // 0..127
    const int c0 = (tid & 1) * 64;      // 0 or 64
    const int grow = m0 + r;
    float sA = 0.0f;
    if (MODE == 0) sA = g_s[grow];
#pragma unroll
    for (int c = 0; c < 64; c += 4) {
        float4 v = *reinterpret_cast<const float4*>(stg + r * 132 + c0 + c);
        const int gcol = n0 + c0 + c;
        if (MODE == 0) {
            const float4 xv = *reinterpret_cast<const float4*>(xin + (size_t)grow * CC + gcol);
            __half2 h0 = __floats2half2_rn(sA * (v.x + sA * xv.x), sA * (v.y + sA * xv.y));
            __half2 h1 = __floats2half2_rn(sA * (v.z + sA * xv.z), sA * (v.w + sA * xv.w));
            uint2 u;
            u.x = *reinterpret_cast<uint32_t*>(&h0);
            u.y = *reinterpret_cast<uint32_t*>(&h1);
            *reinterpret_cast<uint2*>(&g_a2h[(size_t)grow * CC + gcol]) = u;
        } else {
            v.x = (v.x > 0.0f) ? v.x : expm1f(v.x);
            v.y = (v.y > 0.0f) ? v.y : expm1f(v.y);
            v.z = (v.z > 0.0f) ? v.z : expm1f(v.z);
            v.w = (v.w > 0.0f) ? v.w : expm1f(v.w);
            *reinterpret_cast<float4*>(&outp[(size_t)grow * CC + gcol]) = v;
        }
    }
}

// ---------------------------------------------------------------------------
extern "C" void kernel_launch(void* const* d_in, const int* in_sizes, int n_in,
                              void* d_out, int out_size) {
    const float *x = nullptr, *adj = nullptr, *w = nullptr;
    for (int i = 0; i < n_in; i++) {
        if (in_sizes[i] == NN * NN) adj = (const float*)d_in[i];
        else if (in_sizes[i] == NN * CC) x = (const float*)d_in[i];
        else if (in_sizes[i] == CC * CC) w = (const float*)d_in[i];
    }
    float* out = (float*)d_out;

    void *p_xsh = nullptr, *p_a2h = nullptr, *p_wh = nullptr;
    cudaGetSymbolAddress(&p_xsh, g_xsh);
    cudaGetSymbolAddress(&p_a2h, g_a2h);
    cudaGetSymbolAddress(&p_wh, g_wh);

    cudaFuncSetAttribute(gemm_fp16<0>, cudaFuncAttributeMaxDynamicSharedMemorySize, SMEM_BYTES);
    cudaFuncSetAttribute(gemm_fp16<1>, cudaFuncAttributeMaxDynamicSharedMemorySize, SMEM_BYTES);

    rowsum_kernel<<<NN / 8, dim3(32, 8)>>>(adj);
    prep_xs_kernel<<<NN * CC / 4 / 256, 256>>>(x);
    prep_w_kernel<<<CC * CC / 4 / 256, 256>>>(w);
    // grid: blockIdx.x = N tile (2, fast) -> adj row-tile pair co-resident,
    // L2 dedups the A read.
    gemm_fp16<0><<<dim3(2, 64), 256, SMEM_BYTES>>>(
        adj, nullptr, (const __half*)p_xsh, NN / BK, x, nullptr);
    gemm_fp16<1><<<dim3(2, 64), 256, SMEM_BYTES>>>(
        nullptr, (const __half*)p_a2h, (const __half*)p_wh, CC / BK, nullptr, out);
}

// round 7
// speedup vs baseline: 1.2247x; 1.2247x over previous
#include <cuda_runtime.h>
#include <cuda_fp16.h>
#include <mma.h>
#include <cstdint>

using namespace nvcuda;

#define NN 8192
#define CC 256

// ---------------------------------------------------------------------------
// Scratch (__device__ globals; allocation-free rule)
// ---------------------------------------------------------------------------
__device__ float  g_s[NN];                       // d^{-1/2}
__device__ __half g_adjh[(size_t)NN * NN];       // fp16(adj)
__device__ __half g_xsh[NN * CC];                // fp16(s_j * x[j][n])  [K][N]
__device__ __half g_a2h[NN * CC];                // fp16(s_i*(t + s_i*x)) [M][K]
__device__ __half g_wh[CC * CC];                 // fp16(w)  [K][N]

// ---------------------------------------------------------------------------
__device__ __forceinline__ uint32_t smem_u32(const void* p) {
    uint32_t a;
    asm("{ .reg .u64 t; cvta.to.shared.u64 t, %1; cvt.u32.u64 %0, t; }" : "=r"(a) : "l"(p));
    return a;
}
__device__ __forceinline__ void cpa16(uint32_t s, const void* g) {
    asm volatile("cp.async.cg.shared.global [%0], [%1], 16;" :: "r"(s), "l"(g));
}
#define CP_COMMIT() asm volatile("cp.async.commit_group;" ::: "memory")
#define CP_WAIT_2() asm volatile("cp.async.wait_group 2;" ::: "memory")

// ---------------------------------------------------------------------------
// Kernel 1: fused rowsum + f32->fp16 convert of adj.
// ---------------------------------------------------------------------------
__global__ void rowsum_convert_kernel(const float* __restrict__ adj) {
    const int row = blockIdx.x * blockDim.y + threadIdx.y;
    const float4* p = reinterpret_cast<const float4*>(adj + (size_t)row * NN);
    uint2* hout = reinterpret_cast<uint2*>(g_adjh + (size_t)row * NN);
    float sum = 0.0f;
#pragma unroll 4
    for (int i = threadIdx.x; i < NN / 4; i += 32) {
        float4 v = p[i];
        sum += (v.x + v.y) + (v.z + v.w);
        __half2 h0 = __floats2half2_rn(v.x, v.y);
        __half2 h1 = __floats2half2_rn(v.z, v.w);
        uint2 u;
        u.x = *reinterpret_cast<uint32_t*>(&h0);
        u.y = *reinterpret_cast<uint32_t*>(&h1);
        hout[i] = u;
    }
#pragma unroll
    for (int o = 16; o > 0; o >>= 1) sum += __shfl_xor_sync(0xffffffffu, sum, o);
    if (threadIdx.x == 0) g_s[row] = rsqrtf(sum + 1.0f);
}

// ---------------------------------------------------------------------------
__global__ void prep_xs_kernel(const float* __restrict__ x) {
    const int idx = blockIdx.x * 256 + threadIdx.x;   // over NN*CC/4 float4s
    const int row = idx >> 6;                          // CC/4 = 64 per row
    const float s = g_s[row];
    float4 v = reinterpret_cast<const float4*>(x)[idx];
    __half2 h0 = __floats2half2_rn(s * v.x, s * v.y);
    __half2 h1 = __floats2half2_rn(s * v.z, s * v.w);
    uint2 u;
    u.x = *reinterpret_cast<uint32_t*>(&h0);
    u.y = *reinterpret_cast<uint32_t*>(&h1);
    reinterpret_cast<uint2*>(g_xsh)[idx] = u;
}

__global__ void prep_w_kernel(const float* __restrict__ w) {
    const int idx = blockIdx.x * 256 + threadIdx.x;   // over CC*CC/4 float4s
    float4 v = reinterpret_cast<const float4*>(w)[idx];
    __half2 h0 = __floats2half2_rn(v.x, v.y);
    __half2 h1 = __floats2half2_rn(v.z, v.w);
    uint2 u;
    u.x = *reinterpret_cast<uint32_t*>(&h0);
    u.y = *reinterpret_cast<uint32_t*>(&h1);
    reinterpret_cast<uint2*>(g_wh)[idx] = u;
}

// ---------------------------------------------------------------------------
// fp16 WMMA GEMM, 4-stage cp.async, single barrier, reg-dbuf fragments,
// *** fp16 accumulate per BK=64 chunk, promoted to f32 each iteration ***
//   MODE 0: epilogue writes g_a2h = fp16( s_i * (D + s_i * x) )
//   MODE 1: epilogue writes out  = ELU(D)  (f32)
// 256 threads = 8 warps as 4(M) x 2(N); warp tile 32x64.
// ---------------------------------------------------------------------------
constexpr int BM = 128, BN = 128, BK = 64, STAGES = 4;
constexpr int APAD = 72;                   // A smem row stride (halves)
constexpr int BPAD = 136;                  // B smem row stride (halves)
constexpr int A_HALVES = BM * APAD;        // 9216
constexpr int B_HALVES = BK * BPAD;        // 8704
constexpr int STAGE_BYTES = (A_HALVES + B_HALVES) * 2;   // 35840
constexpr int SMEM_BYTES = STAGES * STAGE_BYTES;          // 143360

template <int MODE>
__global__ __launch_bounds__(256, 1)
void gemm_fp16(const __half* __restrict__ A, const __half* __restrict__ B,
               int kA, int k_iters,
               const float* __restrict__ xin, float* __restrict__ outp) {
    extern __shared__ char smem[];
    const uint32_t sb = smem_u32(smem);
    const int tid = threadIdx.x;
    const int warp = tid >> 5;
    const int wm = warp & 3;     // 0..3 along M
    const int wn = warp >> 2;    // 0..1 along N
    const int m0 = blockIdx.y * BM;
    const int n0 = blockIdx.x * BN;

    // per-thread load coords
    const int arr = tid >> 3, arc = (tid & 7) * 8;          // A: 128r x 8 chunks
    const int brr = tid >> 4, brc = (tid & 15) * 8;         // B: 64r x 16 chunks
    const __half* gA = A + (size_t)(m0 + arr) * kA + arc;   // +32 rows per rep
    const __half* gB = B + (size_t)brr * CC + n0 + brc;     // +16 rows per rep
    const uint32_t sAo = (arr * APAD + arc) * 2;
    const uint32_t sBo = A_HALVES * 2 + (brr * BPAD + brc) * 2;

    // persistent f32 accumulation (plain registers)
    float facc[2][4][8];
#pragma unroll
    for (int i = 0; i < 2; i++)
#pragma unroll
        for (int j = 0; j < 4; j++)
#pragma unroll
            for (int e = 0; e < 8; e++) facc[i][j][e] = 0.0f;

    auto load_stage = [&](int kt, int s) {
        const uint32_t st = sb + s * STAGE_BYTES;
        const __half* a = gA + kt * BK;
        const __half* b = gB + (size_t)kt * BK * CC;
#pragma unroll
        for (int r = 0; r < 4; r++)
            cpa16(st + sAo + r * (32 * APAD * 2), a + (size_t)(r * 32) * kA);
#pragma unroll
        for (int r = 0; r < 4; r++)
            cpa16(st + sBo + r * (16 * BPAD * 2), b + (size_t)(r * 16) * CC);
    };

    // prologue: stages 0..2
#pragma unroll
    for (int s = 0; s < STAGES - 1; s++) {
        if (s < k_iters) load_stage(s, s);
        CP_COMMIT();
    }

    for (int kt = 0; kt < k_iters; kt++) {
        CP_WAIT_2();
        __syncthreads();   // protects slot (kt-1)&3 rewrite below

        const int nk = kt + STAGES - 1;
        if (nk < k_iters) load_stage(nk, nk & 3);
        CP_COMMIT();

        const __half* Ap = reinterpret_cast<const __half*>(smem + (kt & 3) * STAGE_BYTES);
        const __half* Bp = Ap + A_HALVES;

        // fp16 chunk accumulators, zeroed per kt
        wmma::fragment<wmma::accumulator, 16, 16, 16, __half> hacc[2][4];
#pragma unroll
        for (int i = 0; i < 2; i++)
#pragma unroll
            for (int j = 0; j < 4; j++)
                wmma::fill_fragment(hacc[i][j], __float2half(0.0f));

        // register double-buffered fragments over 4 k-steps
        wmma::fragment<wmma::matrix_a, 16, 16, 16, __half, wmma::row_major> af[2][2];
        wmma::fragment<wmma::matrix_b, 16, 16, 16, __half, wmma::row_major> bf[2][4];
#pragma unroll
        for (int i = 0; i < 2; i++)
            wmma::load_matrix_sync(af[0][i], Ap + (wm * 32 + i * 16) * APAD, APAD);
#pragma unroll
        for (int j = 0; j < 4; j++)
            wmma::load_matrix_sync(bf[0][j], Bp + wn * 64 + j * 16, BPAD);

#pragma unroll
        for (int ks = 0; ks < 4; ks++) {
            const int cu = ks & 1, nx = cu ^ 1;
            if (ks < 3) {
#pragma unroll
                for (int i = 0; i < 2; i++)
                    wmma::load_matrix_sync(af[nx][i],
                        Ap + (wm * 32 + i * 16) * APAD + (ks + 1) * 16, APAD);
#pragma unroll
                for (int j = 0; j < 4; j++)
                    wmma::load_matrix_sync(bf[nx][j],
                        Bp + ((ks + 1) * 16) * BPAD + wn * 64 + j * 16, BPAD);
            }
#pragma unroll
            for (int i = 0; i < 2; i++)
#pragma unroll
                for (int j = 0; j < 4; j++)
                    wmma::mma_sync(hacc[i][j], af[cu][i], bf[cu][j], hacc[i][j]);
        }

        // promote chunk sums to f32 (element mapping identical across acc types)
#pragma unroll
        for (int i = 0; i < 2; i++)
#pragma unroll
            for (int j = 0; j < 4; j++)
#pragma unroll
                for (int e = 0; e < 8; e++)
                    facc[i][j][e] += __half2float(hacc[i][j].x[e]);
    }
    __syncthreads();   // all MMA smem reads done before staging reuse

    // ---- epilogue: move f32 accum into fragments, stage to smem, writeback ----
    float* stg = reinterpret_cast<float*>(smem);   // 128 x 132
#pragma unroll
    for (int i = 0; i < 2; i++)
#pragma unroll
        for (int j = 0; j < 4; j++) {
            wmma::fragment<wmma::accumulator, 16, 16, 16, float> fa;
#pragma unroll
            for (int e = 0; e < 8; e++) fa.x[e] = facc[i][j][e];
            wmma::store_matrix_sync(stg + (wm * 32 + i * 16) * 132 + wn * 64 + j * 16,
                                    fa, 132, wmma::mem_row_major);
        }
    __syncthreads();

    const int r = tid >> 1;             // 0..127
    const int c0 = (tid & 1) * 64;      // 0 or 64
    const int grow = m0 + r;
    float sA = 0.0f;
    if (MODE == 0) sA = g_s[grow];
#pragma unroll
    for (int c = 0; c < 64; c += 4) {
        float4 v = *reinterpret_cast<const float4*>(stg + r * 132 + c0 + c);
        const int gcol = n0 + c0 + c;
        if (MODE == 0) {
            const float4 xv = *reinterpret_cast<const float4*>(xin + (size_t)grow * CC + gcol);
            __half2 h0 = __floats2half2_rn(sA * (v.x + sA * xv.x), sA * (v.y + sA * xv.y));
            __half2 h1 = __floats2half2_rn(sA * (v.z + sA * xv.z), sA * (v.w + sA * xv.w));
            uint2 u;
            u.x = *reinterpret_cast<uint32_t*>(&h0);
            u.y = *reinterpret_cast<uint32_t*>(&h1);
            *reinterpret_cast<uint2*>(&g_a2h[(size_t)grow * CC + gcol]) = u;
        } else {
            v.x = (v.x > 0.0f) ? v.x : expm1f(v.x);
            v.y = (v.y > 0.0f) ? v.y : expm1f(v.y);
            v.z = (v.z > 0.0f) ? v.z : expm1f(v.z);
            v.w = (v.w > 0.0f) ? v.w : expm1f(v.w);
            *reinterpret_cast<float4*>(&outp[(size_t)grow * CC + gcol]) = v;
        }
    }
}

// ---------------------------------------------------------------------------
extern "C" void kernel_launch(void* const* d_in, const int* in_sizes, int n_in,
                              void* d_out, int out_size) {
    const float *x = nullptr, *adj = nullptr, *w = nullptr;
    for (int i = 0; i < n_in; i++) {
        if (in_sizes[i] == NN * NN) adj = (const float*)d_in[i];
        else if (in_sizes[i] == NN * CC) x = (const float*)d_in[i];
        else if (in_sizes[i] == CC * CC) w = (const float*)d_in[i];
    }
    float* out = (float*)d_out;

    void *p_adjh = nullptr, *p_xsh = nullptr, *p_a2h = nullptr, *p_wh = nullptr;
    cudaGetSymbolAddress(&p_adjh, g_adjh);
    cudaGetSymbolAddress(&p_xsh, g_xsh);
    cudaGetSymbolAddress(&p_a2h, g_a2h);
    cudaGetSymbolAddress(&p_wh, g_wh);

    cudaFuncSetAttribute(gemm_fp16<0>, cudaFuncAttributeMaxDynamicSharedMemorySize, SMEM_BYTES);
    cudaFuncSetAttribute(gemm_fp16<1>, cudaFuncAttributeMaxDynamicSharedMemorySize, SMEM_BYTES);

    rowsum_convert_kernel<<<NN / 8, dim3(32, 8)>>>(adj);
    prep_xs_kernel<<<NN * CC / 4 / 256, 256>>>(x);
    prep_w_kernel<<<CC * CC / 4 / 256, 256>>>(w);
    // grid: blockIdx.x = N tile (2, fast) -> adj row-tile pair co-resident,
    // L2 dedups the A read.
    gemm_fp16<0><<<dim3(2, 64), 256, SMEM_BYTES>>>(
        (const __half*)p_adjh, (const __half*)p_xsh, NN, NN / BK, x, nullptr);
    gemm_fp16<1><<<dim3(2, 64), 256, SMEM_BYTES>>>(
        (const __half*)p_a2h, (const __half*)p_wh, CC, CC / BK, nullptr, out);
}

// round 8
// speedup vs baseline: 1.2487x; 1.0197x over previous
#include <cuda_runtime.h>
#include <cuda_fp16.h>
#include <mma.h>
#include <cstdint>

using namespace nvcuda;

#define NN 8192
#define CC 256

// ---------------------------------------------------------------------------
// Scratch (__device__ globals; allocation-free rule)
// ---------------------------------------------------------------------------
__device__ float  g_s[NN];                       // d^{-1/2}
__device__ __half g_adjh[(size_t)NN * NN];       // fp16(adj)
__device__ __half g_xsh[NN * CC];                // fp16(s_j * x[j][n])  [K][N]
__device__ __half g_a2h[NN * CC];                // fp16(s_i*(t + s_i*x)) [M][K]
__device__ __half g_wh[CC * CC];                 // fp16(w)  [K][N]

// ---------------------------------------------------------------------------
__device__ __forceinline__ uint32_t smem_u32(const void* p) {
    uint32_t a;
    asm("{ .reg .u64 t; cvta.to.shared.u64 t, %1; cvt.u32.u64 %0, t; }" : "=r"(a) : "l"(p));
    return a;
}
__device__ __forceinline__ void cpa16(uint32_t s, const void* g) {
    asm volatile("cp.async.cg.shared.global [%0], [%1], 16;" :: "r"(s), "l"(g));
}
#define CP_COMMIT() asm volatile("cp.async.commit_group;" ::: "memory")
#define CP_WAIT_2() asm volatile("cp.async.wait_group 2;" ::: "memory")

// ---------------------------------------------------------------------------
// Kernel 1: fused rowsum + adj f32->fp16 convert + per-row x scaling.
//   s[i]     = rsqrt(1 + rowsum(adj[i,:]))
//   g_adjh   = fp16(adj)                (streaming hints: evict-first)
//   g_xsh[i] = fp16(s_i * x[i,:])
// one warp per row, 8 rows per block.
// ---------------------------------------------------------------------------
__global__ void rowsum_convert_kernel(const float* __restrict__ adj,
                                      const float* __restrict__ x) {
    const int row = blockIdx.x * blockDim.y + threadIdx.y;
    const int lane = threadIdx.x;
    const float4* p = reinterpret_cast<const float4*>(adj + (size_t)row * NN);
    uint2* hout = reinterpret_cast<uint2*>(g_adjh + (size_t)row * NN);
    float sum = 0.0f;
#pragma unroll 8
    for (int i = lane; i < NN / 4; i += 32) {
        float4 v = __ldcs(p + i);
        sum += (v.x + v.y) + (v.z + v.w);
        __half2 h0 = __floats2half2_rn(v.x, v.y);
        __half2 h1 = __floats2half2_rn(v.z, v.w);
        uint2 u;
        u.x = *reinterpret_cast<uint32_t*>(&h0);
        u.y = *reinterpret_cast<uint32_t*>(&h1);
        __stcs(hout + i, u);
    }
#pragma unroll
    for (int o = 16; o > 0; o >>= 1) sum += __shfl_xor_sync(0xffffffffu, sum, o);
    const float s = rsqrtf(__shfl_sync(0xffffffffu, sum, 0) + 1.0f);
    if (lane == 0) g_s[row] = s;

    // fused x-prep for this row: 256 floats -> 256 halves (2 float4 per lane)
    const float4* xp = reinterpret_cast<const float4*>(x + (size_t)row * CC);
    uint2* xo = reinterpret_cast<uint2*>(g_xsh + (size_t)row * CC);
#pragma unroll
    for (int i = lane; i < CC / 4; i += 32) {
        float4 v = xp[i];
        __half2 h0 = __floats2half2_rn(s * v.x, s * v.y);
        __half2 h1 = __floats2half2_rn(s * v.z, s * v.w);
        uint2 u;
        u.x = *reinterpret_cast<uint32_t*>(&h0);
        u.y = *reinterpret_cast<uint32_t*>(&h1);
        xo[i] = u;
    }
}

// ---------------------------------------------------------------------------
__global__ void prep_w_kernel(const float* __restrict__ w) {
    const int idx = blockIdx.x * 256 + threadIdx.x;   // over CC*CC/4 float4s
    float4 v = reinterpret_cast<const float4*>(w)[idx];
    __half2 h0 = __floats2half2_rn(v.x, v.y);
    __half2 h1 = __floats2half2_rn(v.z, v.w);
    uint2 u;
    u.x = *reinterpret_cast<uint32_t*>(&h0);
    u.y = *reinterpret_cast<uint32_t*>(&h1);
    reinterpret_cast<uint2*>(g_wh)[idx] = u;
}

// ---------------------------------------------------------------------------
// fp16 WMMA GEMM (R4 champion): 128x128 tile, BK=64, 4-stage cp.async,
// single barrier per K-iter, register double-buffered fragments, f32 acc.
//   MODE 0: epilogue writes g_a2h = fp16( s_i * (D + s_i * x) )
//   MODE 1: epilogue writes out  = ELU(D)  (f32)
// 256 threads = 8 warps as 4(M) x 2(N); warp tile 32x64.
// ---------------------------------------------------------------------------
constexpr int BM = 128, BN = 128, BK = 64, STAGES = 4;
constexpr int APAD = 72;                   // A smem row stride (halves)
constexpr int BPAD = 136;                  // B smem row stride (halves)
constexpr int A_HALVES = BM * APAD;        // 9216
constexpr int B_HALVES = BK * BPAD;        // 8704
constexpr int STAGE_BYTES = (A_HALVES + B_HALVES) * 2;   // 35840
constexpr int SMEM_BYTES = STAGES * STAGE_BYTES;          // 143360

template <int MODE>
__global__ __launch_bounds__(256, 1)
void gemm_fp16(const __half* __restrict__ A, const __half* __restrict__ B,
               int kA, int k_iters,
               const float* __restrict__ xin, float* __restrict__ outp) {
    extern __shared__ char smem[];
    const uint32_t sb = smem_u32(smem);
    const int tid = threadIdx.x;
    const int warp = tid >> 5;
    const int wm = warp & 3;     // 0..3 along M
    const int wn = warp >> 2;    // 0..1 along N
    const int m0 = blockIdx.y * BM;
    const int n0 = blockIdx.x * BN;

    // per-thread load coords
    const int arr = tid >> 3, arc = (tid & 7) * 8;          // A: 128r x 8 chunks
    const int brr = tid >> 4, brc = (tid & 15) * 8;         // B: 64r x 16 chunks
    const __half* gA = A + (size_t)(m0 + arr) * kA + arc;   // +32 rows per rep
    const __half* gB = B + (size_t)brr * CC + n0 + brc;     // +16 rows per rep
    const uint32_t sAo = (arr * APAD + arc) * 2;
    const uint32_t sBo = A_HALVES * 2 + (brr * BPAD + brc) * 2;

    wmma::fragment<wmma::accumulator, 16, 16, 16, float> acc[2][4];
#pragma unroll
    for (int i = 0; i < 2; i++)
#pragma unroll
        for (int j = 0; j < 4; j++) wmma::fill_fragment(acc[i][j], 0.0f);

    auto load_stage = [&](int kt, int s) {
        const uint32_t st = sb + s * STAGE_BYTES;
        const __half* a = gA + kt * BK;
        const __half* b = gB + (size_t)kt * BK * CC;
#pragma unroll
        for (int r = 0; r < 4; r++)
            cpa16(st + sAo + r * (32 * APAD * 2), a + (size_t)(r * 32) * kA);
#pragma unroll
        for (int r = 0; r < 4; r++)
            cpa16(st + sBo + r * (16 * BPAD * 2), b + (size_t)(r * 16) * CC);
    };

    // prologue: stages 0..2
#pragma unroll
    for (int s = 0; s < STAGES - 1; s++) {
        if (s < k_iters) load_stage(s, s);
        CP_COMMIT();
    }

    for (int kt = 0; kt < k_iters; kt++) {
        CP_WAIT_2();
        __syncthreads();   // protects slot (kt-1)&3 rewrite below

        const int nk = kt + STAGES - 1;
        if (nk < k_iters) load_stage(nk, nk & 3);
        CP_COMMIT();

        const __half* Ap = reinterpret_cast<const __half*>(smem + (kt & 3) * STAGE_BYTES);
        const __half* Bp = Ap + A_HALVES;

        // register double-buffered fragments over 4 k-steps
        wmma::fragment<wmma::matrix_a, 16, 16, 16, __half, wmma::row_major> af[2][2];
        wmma::fragment<wmma::matrix_b, 16, 16, 16, __half, wmma::row_major> bf[2][4];
#pragma unroll
        for (int i = 0; i < 2; i++)
            wmma::load_matrix_sync(af[0][i], Ap + (wm * 32 + i * 16) * APAD, APAD);
#pragma unroll
        for (int j = 0; j < 4; j++)
            wmma::load_matrix_sync(bf[0][j], Bp + wn * 64 + j * 16, BPAD);

#pragma unroll
        for (int ks = 0; ks < 4; ks++) {
            const int cu = ks & 1, nx = cu ^ 1;
            if (ks < 3) {
#pragma unroll
                for (int i = 0; i < 2; i++)
                    wmma::load_matrix_sync(af[nx][i],
                        Ap + (wm * 32 + i * 16) * APAD + (ks + 1) * 16, APAD);
#pragma unroll
                for (int j = 0; j < 4; j++)
                    wmma::load_matrix_sync(bf[nx][j],
                        Bp + ((ks + 1) * 16) * BPAD + wn * 64 + j * 16, BPAD);
            }
#pragma unroll
            for (int i = 0; i < 2; i++)
#pragma unroll
                for (int j = 0; j < 4; j++)
                    wmma::mma_sync(acc[i][j], af[cu][i], bf[cu][j], acc[i][j]);
        }
    }
    __syncthreads();   // all MMA smem reads done before staging reuse

    // ---- epilogue: stage accumulators to smem (f32), then fused writeback ----
    float* stg = reinterpret_cast<float*>(smem);   // 128 x 132
#pragma unroll
    for (int i = 0; i < 2; i++)
#pragma unroll
        for (int j = 0; j < 4; j++)
            wmma::store_matrix_sync(stg + (wm * 32 + i * 16) * 132 + wn * 64 + j * 16,
                                    acc[i][j], 132, wmma::mem_row_major);
    __syncthreads();

    const int r = tid >> 1;             // 0..127
    const int c0 = (tid & 1) * 64;      // 0 or 64
    const int grow = m0 + r;
    float sA = 0.0f;
    if (MODE == 0) sA = g_s[grow];
#pragma unroll
    for (int c = 0; c < 64; c += 4) {
        float4 v = *reinterpret_cast<const float4*>(stg + r * 132 + c0 + c);
        const int gcol = n0 + c0 + c;
        if (MODE == 0) {
            const float4 xv = *reinterpret_cast<const float4*>(xin + (size_t)grow * CC + gcol);
            __half2 h0 = __floats2half2_rn(sA * (v.x + sA * xv.x), sA * (v.y + sA * xv.y));
            __half2 h1 = __floats2half2_rn(sA * (v.z + sA * xv.z), sA * (v.w + sA * xv.w));
            uint2 u;
            u.x = *reinterpret_cast<uint32_t*>(&h0);
            u.y = *reinterpret_cast<uint32_t*>(&h1);
            *reinterpret_cast<uint2*>(&g_a2h[(size_t)grow * CC + gcol]) = u;
        } else {
            v.x = (v.x > 0.0f) ? v.x : expm1f(v.x);
            v.y = (v.y > 0.0f) ? v.y : expm1f(v.y);
            v.z = (v.z > 0.0f) ? v.z : expm1f(v.z);
            v.w = (v.w > 0.0f) ? v.w : expm1f(v.w);
            *reinterpret_cast<float4*>(&outp[(size_t)grow * CC + gcol]) = v;
        }
    }
}

// ---------------------------------------------------------------------------
extern "C" void kernel_launch(void* const* d_in, const int* in_sizes, int n_in,
                              void* d_out, int out_size) {
    const float *x = nullptr, *adj = nullptr, *w = nullptr;
    for (int i = 0; i < n_in; i++) {
        if (in_sizes[i] == NN * NN) adj = (const float*)d_in[i];
        else if (in_sizes[i] == NN * CC) x = (const float*)d_in[i];
        else if (in_sizes[i] == CC * CC) w = (const float*)d_in[i];
    }
    float* out = (float*)d_out;

    void *p_adjh = nullptr, *p_xsh = nullptr, *p_a2h = nullptr, *p_wh = nullptr;
    cudaGetSymbolAddress(&p_adjh, g_adjh);
    cudaGetSymbolAddress(&p_xsh, g_xsh);
    cudaGetSymbolAddress(&p_a2h, g_a2h);
    cudaGetSymbolAddress(&p_wh, g_wh);

    cudaFuncSetAttribute(gemm_fp16<0>, cudaFuncAttributeMaxDynamicSharedMemorySize, SMEM_BYTES);
    cudaFuncSetAttribute(gemm_fp16<1>, cudaFuncAttributeMaxDynamicSharedMemorySize, SMEM_BYTES);

    prep_w_kernel<<<CC * CC / 4 / 256, 256>>>(w);          // independent, first
    rowsum_convert_kernel<<<NN / 8, dim3(32, 8)>>>(adj, x); // s + adjh + xsh fused
    // grid: blockIdx.x = N tile (2, fast) -> adj row-tile pair co-resident,
    // L2 dedups the A read.
    gemm_fp16<0><<<dim3(2, 64), 256, SMEM_BYTES>>>(
        (const __half*)p_adjh, (const __half*)p_xsh, NN, NN / BK, x, nullptr);
    gemm_fp16<1><<<dim3(2, 64), 256, SMEM_BYTES>>>(
        (const __half*)p_a2h, (const __half*)p_wh, CC, CC / BK, nullptr, out);
}